// round 12
// baseline (speedup 1.0000x reference)
#include <cuda_runtime.h>

// GridToGraphConverter: B=4, C=16, H=W=512
//  out layout (float32, concatenated):
//   [0, NF)            node_features  (B*HW, C)
//   [NF, NF+E)         edge_index src row
//   [NF+E, NF+2E)      edge_index dst row
//   [NF+2E, NF+2E+2E)  edge_attr (E, 2)
// edge_index / edge offsets generated analytically (grid-8 structure).
//
// Quad of 4 threads shares a 4-node group; each quad thread accumulates 4 of
// the 16 channels (x4 batches). Intra-warp halo via stride-4 shuffles +
// in-loop exports exchanged post-loop by shfl. WARP-boundary halo no longer
// uses per-plane scattered loads: edge lanes stash their boundary up/dn
// scalars per ci (predicated STS.64) and, once per batch after a sync, the
// opposite edge thread computes the 3 cross-boundary sums from the stash +
// retained nf registers. Block-edge threads (8/block) keep local loads.
// Interior rows emit their contiguous edge range coalesced via smem park.

#define Wd 512
#define Hd 512
#define HWd (Wd * Hd)
#define Cc 16
#define Bb 4
#define NFSZ (Bb * HWd * Cc)        // 16777216
#define Ed 2091012
#define SS 260                       // smem stride (256 cols + pad)

__global__ __launch_bounds__(256, 3) void g2g_kernel(const float* __restrict__ grid,
                                                     float* __restrict__ out) {
    __shared__ float sm[8 * SS];            // emission park [slot][col]
    __shared__ float2 sm_st[2][7][2][4][4]; // [buf][bd][side][q][ci] (up,dn)
    __shared__ float4 sm_nf[2][7][2][4];    // [buf][bd][side][q] own-row nf

    const int tid = threadIdx.x;
    const int h = blockIdx.x >> 1;          // row
    const int half = blockIdx.x & 1;        // half-row
    const int q = tid & 3;                  // channel quad id
    const int lane = tid & 31;
    const int w = tid >> 5;                 // warp id
    const int wg = half * 256 + (tid & ~3); // first column of 4-node group
    const int n0 = h * Wd + wg;             // first node of group

    const bool hasUp = (h > 0);
    const bool hasDn = (h < Hd - 1);
    const bool hasL = (wg > 0);
    const bool hasR = (wg < Wd - 4);

    const int oUp = hasUp ? n0 - Wd : n0;
    const int oDn = hasDn ? n0 + Wd : n0;

    // Block-edge threads (8 per block): keep local clamped loads.
    const bool bEdgeL = (tid < 4);
    const bool bEdgeR = (tid >= 252);
    const bool bEdge = bEdgeL || bEdgeR;
    const int oEm = bEdgeL ? (hasL ? n0 - 1 : n0) : (hasR ? n0 + 4 : n0);
    const int oEu = bEdgeL ? (hasL ? oUp - 1 : oUp) : (hasR ? oUp + 4 : oUp);
    const int oEd = bEdgeL ? (hasL ? oDn - 1 : oDn) : (hasR ? oDn + 4 : oDn);

    // Warp-boundary (non-block-edge) lanes use the stash protocol.
    const bool leftW = (lane < 4) && !bEdgeL;
    const bool rightW = (lane >= 28) && !bEdgeR;
    const bool edgeW = leftW || rightW;
    const int bdW = rightW ? w : (w - 1);   // boundary id I write to
    const int sdW = rightW ? 0 : 1;         // side 0 = right-edge(T) writes

    float acc[4][8];
#pragma unroll
    for (int i = 0; i < 4; i++)
#pragma unroll
        for (int k = 0; k < 8; k++) acc[i][k] = 0.0f;
    float e0 = 0.0f, e1 = 0.0f, e2 = 0.0f, e3 = 0.0f;   // diag exports

    for (int b = 0; b < Bb; b++) {
        const float* pb = grid + (size_t)b * (Cc * HWd);
        const int buf = b & 1;
        float nf[4][4];              // [node i][ci] channel-quad collection
#pragma unroll
        for (int ci = 0; ci < 4; ci++) {
            const int c = q * 4 + ci;           // this thread's channel
            const float* p = pb + c * HWd;
            float4 ow = *(const float4*)(p + n0);
            float4 up = *(const float4*)(p + oUp);
            float4 dn = *(const float4*)(p + oDn);
            nf[0][ci] = ow.x;
            nf[1][ci] = ow.y;
            nf[2][ci] = ow.z;
            nf[3][ci] = ow.w;

            // mid-row neighbor values via quad-stride shuffles
            float mL = __shfl_up_sync(0xffffffffu, ow.w, 4);
            float mR = __shfl_down_sync(0xffffffffu, ow.x, 4);
            if (bEdge) {            // block edge: real loads (clamped)
                float v = p[oEm];
                if (bEdgeL) {
                    mL = v;
                    acc[0][0] += fabsf(ow.x - p[oEu]);
                    acc[0][5] += fabsf(ow.x - p[oEd]);
                } else {
                    mR = v;
                    acc[3][2] += fabsf(ow.w - p[oEu]);
                    acc[3][7] += fabsf(ow.w - p[oEd]);
                }
            }
            // warp-edge lanes: zero-contribution placeholders (fixed per-b)
            if (leftW) mL = ow.x;
            if (rightW) mR = ow.w;
            // stash boundary up/dn scalars for the opposite side
            if (edgeW) {
                sm_st[buf][bdW][sdW][q][ci] =
                    rightW ? make_float2(up.w, dn.w) : make_float2(up.x, dn.x);
            }

            // node 0 (slots 0,5 cross-group; slot 3 mid)
            acc[0][1] += fabsf(ow.x - up.x);
            acc[0][2] += fabsf(ow.x - up.y);
            acc[0][3] += fabsf(ow.x - mL);
            acc[0][4] += fabsf(ow.x - ow.y);
            acc[0][6] += fabsf(ow.x - dn.x);
            acc[0][7] += fabsf(ow.x - dn.y);
            // node 1 (all local)
            acc[1][0] += fabsf(ow.y - up.x);
            acc[1][1] += fabsf(ow.y - up.y);
            acc[1][2] += fabsf(ow.y - up.z);
            acc[1][3] += fabsf(ow.y - ow.x);
            acc[1][4] += fabsf(ow.y - ow.z);
            acc[1][5] += fabsf(ow.y - dn.x);
            acc[1][6] += fabsf(ow.y - dn.y);
            acc[1][7] += fabsf(ow.y - dn.z);
            // node 2 (all local)
            acc[2][0] += fabsf(ow.z - up.y);
            acc[2][1] += fabsf(ow.z - up.z);
            acc[2][2] += fabsf(ow.z - up.w);
            acc[2][3] += fabsf(ow.z - ow.y);
            acc[2][4] += fabsf(ow.z - ow.w);
            acc[2][5] += fabsf(ow.z - dn.y);
            acc[2][6] += fabsf(ow.z - dn.z);
            acc[2][7] += fabsf(ow.z - dn.w);
            // node 3 (slots 2,7 cross-group; slot 4 mid)
            acc[3][0] += fabsf(ow.w - up.z);
            acc[3][1] += fabsf(ow.w - up.w);
            acc[3][3] += fabsf(ow.w - ow.z);
            acc[3][4] += fabsf(ow.w - mR);
            acc[3][5] += fabsf(ow.w - dn.z);
            acc[3][6] += fabsf(ow.w - dn.w);
            // diag exports for intra-warp neighbor groups
            e0 += fabsf(mL - up.x);   // left nb node3 slot2
            e1 += fabsf(mL - dn.x);   // left nb node3 slot7
            e2 += fabsf(mR - up.w);   // right nb node0 slot0
            e3 += fabsf(mR - dn.w);   // right nb node0 slot5
        }
        // stash own-row boundary nf for the opposite side
        if (edgeW) {
            float* s = rightW ? &nf[3][0] : &nf[0][0];
            sm_nf[buf][bdW][sdW][q] = make_float4(s[0], s[1], s[2], s[3]);
        }
        __syncthreads();
        // per-batch boundary fix-up (adds the true cross-warp sums)
        if (rightW) {   // T: needs S's own.x (nf) and up.x/dn.x (stash)
            float4 nS = sm_nf[buf][w][1][q];
            const float* ns = &nS.x;
#pragma unroll
            for (int ci = 0; ci < 4; ci++) {
                float2 st = sm_st[buf][w][1][q][ci];
                float o = nf[3][ci];
                acc[3][4] += fabsf(o - ns[ci]);
                acc[3][2] += fabsf(o - st.x);
                acc[3][7] += fabsf(o - st.y);
            }
        }
        if (leftW) {    // S: needs T's own.w (nf) and up.w/dn.w (stash)
            float4 nT = sm_nf[buf][w - 1][0][q];
            const float* nt = &nT.x;
#pragma unroll
            for (int ci = 0; ci < 4; ci++) {
                float2 st = sm_st[buf][w - 1][0][q][ci];
                float o = nf[0][ci];
                acc[0][3] += fabsf(o - nt[ci]);
                acc[0][0] += fabsf(o - st.x);
                acc[0][5] += fabsf(o - st.y);
            }
        }
        // Direct node_features store: node (n0+i), channels 4q..4q+3.
        float* dstb = out + (size_t)b * (HWd * Cc);
#pragma unroll
        for (int i = 0; i < 4; i++) {
            *(float4*)(dstb + (size_t)(n0 + i) * Cc + 4 * q) =
                make_float4(nf[i][0], nf[i][1], nf[i][2], nf[i][3]);
        }
    }

    // ---- Intra-warp diag export exchange via shuffles ----
    {
        float rA = __shfl_down_sync(0xffffffffu, e0, 4);
        float rB = __shfl_down_sync(0xffffffffu, e1, 4);
        float rC = __shfl_up_sync(0xffffffffu, e2, 4);
        float rD = __shfl_up_sync(0xffffffffu, e3, 4);
        if (lane < 28) {    // right neighbor intra-warp: its e0,e1
            acc[3][2] = rA;
            acc[3][7] = rB;
        }
        if (lane >= 4) {    // left neighbor intra-warp: its e2,e3
            acc[0][0] = rC;
            acc[0][5] = rD;
        }
    }

    // ---- Selective quad reduce: lane ends with ONLY node q's 8 sums ----
    const float inv64 = 1.0f / 64.0f;
    const int p1 = q & 1;
    float a[8];
#pragma unroll
    for (int k = 0; k < 8; k++) {
        float sA = p1 ? acc[0][k] : acc[1][k];      // send node (1-p1)
        float sB = p1 ? acc[2][k] : acc[3][k];      // send node (1-p1)+2
        float rA = __shfl_xor_sync(0xffffffffu, sA, 1);
        float rB = __shfl_xor_sync(0xffffffffu, sB, 1);
        float kA = (p1 ? acc[1][k] : acc[0][k]) + rA;   // node p1 pair-sum
        float kB = (p1 ? acc[3][k] : acc[2][k]) + rB;   // node p1+2 pair-sum
        float s2 = (q & 2) ? kA : kB;               // send what partner keeps
        float r2 = __shfl_xor_sync(0xffffffffu, s2, 2);
        a[k] = (((q & 2) ? kB : kA) + r2) * inv64;
    }

    const float SQ2 = 1.41421356237309515f;
    float* eiS = out + NFSZ;
    float* eiD = out + NFSZ + Ed;
    float* ea  = out + NFSZ + 2 * Ed;
    const bool boundaryRow = (h == 0) || (h == Hd - 1);

    if (!boundaryRow) {
        __syncthreads();    // protect sm reuse ordering
        // Park per-slot sums: sm[slot][col_l] (conflict-free both ways).
#pragma unroll
        for (int k = 0; k < 8; k++) sm[k * SS + tid] = a[k];
        __syncthreads();

        // Coalesced emission over this half-row's contiguous 2045 edges.
        const int eBase = 2556 + (h - 1) * 4090 + half * 2045;
#pragma unroll
        for (int it = 0; it < 8; it++) {
            int le = it * 256 + tid;
            if (le < 2045) {
                int col_l, slot;
                if (half == 0) {
                    if (le < 5) {               // col 0: slots {1,2,4,6,7}
                        col_l = 0;
                        slot = (0x76421 >> (4 * le)) & 0xF;
                    } else {
                        int j = le - 5;
                        col_l = 1 + (j >> 3);
                        slot = j & 7;
                    }
                } else {
                    if (le < 2040) {
                        col_l = le >> 3;
                        slot = le & 7;
                    } else {                    // col 511: slots {0,1,3,5,6}
                        col_l = 255;
                        slot = (0x65310 >> (4 * (le - 2040))) & 0xF;
                    }
                }
                int dh = (slot < 3) ? -1 : ((slot >= 5) ? 1 : 0);
                int dw = ((0x42 >> slot) & 1) ? 0
                         : (((0x29 >> slot) & 1) ? -1 : 1);
                float ds = ((0xA5 >> slot) & 1) ? SQ2 : 1.0f;

                int nn = h * Wd + half * 256 + col_l;
                int e = eBase + le;
                eiS[e] = (float)nn;
                eiD[e] = (float)(nn + dh * Wd + dw);
                *(float2*)(ea + 2 * e) = make_float2(ds, sm[slot * SS + col_l]);
            }
        }
    } else {
        // Boundary rows (h = 0 or 511): scattered per-node emission (2 rows).
        const int col = half * 256 + tid;
        const int dnk[8] = {-513, -512, -511, -1, 1, 511, 512, 513};
        const float dist[8] = {SQ2, 1.0f, SQ2, 1.0f, 1.0f, SQ2, 1.0f, SQ2};
        const int rowBase = (h == 0) ? 0 : 2556 + (h - 1) * 4090;
        int e = rowBase + ((col == 0) ? 0 : 3 + (col - 1) * 5);

        const int n = h * Wd + col;
        const bool vL = (col > 0);
        const bool vR = (col < Wd - 1);
        bool val[8] = {hasUp && vL, hasUp, hasUp && vR,
                       vL, vR,
                       hasDn && vL, hasDn, hasDn && vR};
#pragma unroll
        for (int k = 0; k < 8; k++) {
            if (val[k]) {
                eiS[e] = (float)n;
                eiD[e] = (float)(n + dnk[k]);
                ea[2 * e]     = dist[k];
                ea[2 * e + 1] = a[k];
                e++;
            }
        }
    }
}

extern "C" void kernel_launch(void* const* d_in, const int* in_sizes, int n_in,
                              void* d_out, int out_size) {
    const float* grid = (const float*)d_in[0];
    float* out = (float*)d_out;
    // 1024 blocks x 256 threads: each block = half a grid row
    g2g_kernel<<<1024, 256>>>(grid, out);
}

// round 13
// speedup vs baseline: 1.5108x; 1.5108x over previous
#include <cuda_runtime.h>

// GridToGraphConverter: B=4, C=16, H=W=512
//  out layout (float32, concatenated):
//   [0, NF)            node_features  (B*HW, C)
//   [NF, NF+E)         edge_index src row
//   [NF+E, NF+2E)      edge_index dst row
//   [NF+2E, NF+2E+2E)  edge_attr (E, 2)
//
// Two-kernel scheme exploiting |src-dst| symmetry:
//  K1: per node, accumulate only the 4 DOWN/RIGHT direction sums
//      (R, DL, D, DR) -> loads just own+down rows (2x float4 per plane
//      instead of 3x), no smem, no barriers; writes sums to a 4MB
//      __device__ scratch + node_features directly.
//  K2: emits edge_index + edge_attr fully coalesced via the analytic
//      inverse edge->(col,slot) map; up/left slots read the neighbor's
//      down/right scratch entry (symmetry).

#define Wd 512
#define Hd 512
#define HWd (Wd * Hd)
#define Cc 16
#define Bb 4
#define NFSZ (Bb * HWd * Cc)        // 16777216
#define Ed 2091012

// scratch: [h][k][col], k: 0=R, 1=DL, 2=D, 3=DR (already /64)
__device__ float g_scr[Hd][4][Wd];

__global__ __launch_bounds__(256, 4) void g2g_k1(const float* __restrict__ grid,
                                                 float* __restrict__ out) {
    const int tid = threadIdx.x;
    const int h = blockIdx.x >> 1;          // row
    const int half = blockIdx.x & 1;        // half-row
    const int q = tid & 3;                  // channel quad id
    const int lane = tid & 31;
    const int wg = half * 256 + (tid & ~3); // first column of 4-node group
    const int n0 = h * Wd + wg;

    const bool hasDn = (h < Hd - 1);
    const bool hasL = (wg > 0);
    const bool hasR = (wg < Wd - 4);

    const int oDn = hasDn ? n0 + Wd : n0;   // clamped (garbage unread)
    const int oLd = hasL ? oDn - 1 : oDn;   // down-left fallback
    const int oRm = hasR ? n0 + 4 : n0;     // mid-right fallback
    const int oRd = hasR ? oDn + 4 : oDn;   // down-right fallback
    const bool leftLane = (lane < 4);
    const bool rightLane = (lane >= 28);

    float acc[4][4];                        // [node][k] k:0=R,1=DL,2=D,3=DR
#pragma unroll
    for (int i = 0; i < 4; i++)
#pragma unroll
        for (int k = 0; k < 4; k++) acc[i][k] = 0.0f;

    for (int b = 0; b < Bb; b++) {
        const float* pb = grid + (size_t)b * (Cc * HWd);
        float nf[4][4];
#pragma unroll
        for (int ci = 0; ci < 4; ci++) {
            const int c = q * 4 + ci;
            const float* p = pb + c * HWd;
            float4 ow = *(const float4*)(p + n0);
            float4 dn = *(const float4*)(p + oDn);
            nf[0][ci] = ow.x;
            nf[1][ci] = ow.y;
            nf[2][ci] = ow.z;
            nf[3][ci] = ow.w;

            // cross-group neighbor values (quad-stride shuffles; edge lanes
            // fall back to clamped global loads — works across blocks too)
            float mR = __shfl_down_sync(0xffffffffu, ow.x, 4);
            float dR = __shfl_down_sync(0xffffffffu, dn.x, 4);
            float dL = __shfl_up_sync(0xffffffffu, dn.w, 4);
            if (rightLane) {
                mR = p[oRm];
                dR = p[oRd];
            }
            if (leftLane) dL = p[oLd];

            // down/right sums only
            acc[0][0] += fabsf(ow.x - ow.y);
            acc[0][1] += fabsf(ow.x - dL);
            acc[0][2] += fabsf(ow.x - dn.x);
            acc[0][3] += fabsf(ow.x - dn.y);

            acc[1][0] += fabsf(ow.y - ow.z);
            acc[1][1] += fabsf(ow.y - dn.x);
            acc[1][2] += fabsf(ow.y - dn.y);
            acc[1][3] += fabsf(ow.y - dn.z);

            acc[2][0] += fabsf(ow.z - ow.w);
            acc[2][1] += fabsf(ow.z - dn.y);
            acc[2][2] += fabsf(ow.z - dn.z);
            acc[2][3] += fabsf(ow.z - dn.w);

            acc[3][0] += fabsf(ow.w - mR);
            acc[3][1] += fabsf(ow.w - dn.z);
            acc[3][2] += fabsf(ow.w - dn.w);
            acc[3][3] += fabsf(ow.w - dR);
        }
        // Direct node_features store: node (n0+i), channels 4q..4q+3.
        float* dstb = out + (size_t)b * (HWd * Cc);
#pragma unroll
        for (int i = 0; i < 4; i++) {
            *(float4*)(dstb + (size_t)(n0 + i) * Cc + 4 * q) =
                make_float4(nf[i][0], nf[i][1], nf[i][2], nf[i][3]);
        }
    }

    // Selective quad reduce: thread ends with node q's 4 sums (col = wg+q).
    const float inv64 = 1.0f / 64.0f;
    const int p1 = q & 1;
    float a[4];
#pragma unroll
    for (int k = 0; k < 4; k++) {
        float sA = p1 ? acc[0][k] : acc[1][k];
        float sB = p1 ? acc[2][k] : acc[3][k];
        float rA = __shfl_xor_sync(0xffffffffu, sA, 1);
        float rB = __shfl_xor_sync(0xffffffffu, sB, 1);
        float kA = (p1 ? acc[1][k] : acc[0][k]) + rA;
        float kB = (p1 ? acc[3][k] : acc[2][k]) + rB;
        float s2 = (q & 2) ? kA : kB;
        float r2 = __shfl_xor_sync(0xffffffffu, s2, 2);
        a[k] = (((q & 2) ? kB : kA) + r2) * inv64;
    }

    // Coalesced scratch write: col = half*256 + tid.
    const int col = half * 256 + tid;
#pragma unroll
    for (int k = 0; k < 4; k++) g_scr[h][k][col] = a[k];
}

__global__ __launch_bounds__(256) void g2g_k2(float* __restrict__ out) {
    const int tid = threadIdx.x;
    const int h = blockIdx.x >> 1;
    const int half = blockIdx.x & 1;

    const float SQ2 = 1.41421356237309515f;
    float* eiS = out + NFSZ;
    float* eiD = out + NFSZ + Ed;
    float* ea  = out + NFSZ + 2 * Ed;

    const bool boundaryRow = (h == 0) || (h == Hd - 1);
    const int cnt = boundaryRow ? 1278 : 2045;
    const int rowBase = (h == 0) ? 0 : 2556 + (h - 1) * 4090;
    const int eBase = rowBase + half * cnt;

#pragma unroll
    for (int it = 0; it < 8; it++) {
        int le = it * 256 + tid;
        if (le >= cnt) break;
        int col_l, slot;
        if (!boundaryRow) {
            if (half == 0) {
                if (le < 5) {               // col 0: slots {1,2,4,6,7}
                    col_l = 0;
                    slot = (0x76421 >> (4 * le)) & 0xF;
                } else {
                    int j = le - 5;
                    col_l = 1 + (j >> 3);
                    slot = j & 7;
                }
            } else {
                if (le < 2040) {
                    col_l = le >> 3;
                    slot = le & 7;
                } else {                    // col 511: slots {0,1,3,5,6}
                    col_l = 255;
                    slot = (0x65310 >> (4 * (le - 2040))) & 0xF;
                }
            }
        } else if (h == 0) {                // slots 3..7 only
            if (half == 0) {
                if (le < 3) {               // col 0: {4,6,7}
                    col_l = 0;
                    slot = (le == 0) ? 4 : (le == 1) ? 6 : 7;
                } else {
                    int j = le - 3;
                    int d = j / 5;
                    col_l = 1 + d;
                    slot = 3 + (j - d * 5);
                }
            } else {
                if (le < 1275) {
                    int d = le / 5;
                    col_l = d;
                    slot = 3 + (le - d * 5);
                } else {                    // col 511: {3,5,6}
                    col_l = 255;
                    int r = le - 1275;
                    slot = (r == 0) ? 3 : (r == 1) ? 5 : 6;
                }
            }
        } else {                            // h == 511: slots 0..4 only
            if (half == 0) {
                if (le < 3) {               // col 0: {1,2,4}
                    col_l = 0;
                    slot = (le == 0) ? 1 : (le == 1) ? 2 : 4;
                } else {
                    int j = le - 3;
                    int d = j / 5;
                    col_l = 1 + d;
                    slot = j - d * 5;
                }
            } else {
                if (le < 1275) {
                    int d = le / 5;
                    col_l = d;
                    slot = le - d * 5;
                } else {                    // col 511: {0,1,3}
                    col_l = 255;
                    int r = le - 1275;
                    slot = (r == 0) ? 0 : (r == 1) ? 1 : 3;
                }
            }
        }

        int col = half * 256 + col_l;
        int dh = (slot < 3) ? -1 : ((slot >= 5) ? 1 : 0);
        int dw = ((0x42 >> slot) & 1) ? 0 : (((0x29 >> slot) & 1) ? -1 : 1);
        float ds = ((0xA5 >> slot) & 1) ? SQ2 : 1.0f;

        // symmetry map: up/left slots read the neighbor's down/right sum
        int sh, sk, sc;
        if (slot < 3) {         // UL,U,UR -> (h-1, {DR,D,DL}, col+slot-1)
            sh = h - 1;
            sk = 3 - slot;
            sc = col + slot - 1;
        } else if (slot == 3) { // L -> (h, R, col-1)
            sh = h;
            sk = 0;
            sc = col - 1;
        } else {                // R,DL,D,DR -> own entry
            sh = h;
            sk = slot - 4;
            sc = col;
        }
        float fd = g_scr[sh][sk][sc];

        int nn = h * Wd + col;
        int e = eBase + le;
        eiS[e] = (float)nn;
        eiD[e] = (float)(nn + dh * Wd + dw);
        *(float2*)(ea + 2 * e) = make_float2(ds, fd);
    }
}

extern "C" void kernel_launch(void* const* d_in, const int* in_sizes, int n_in,
                              void* d_out, int out_size) {
    const float* grid = (const float*)d_in[0];
    float* out = (float*)d_out;
    g2g_k1<<<1024, 256>>>(grid, out);   // compute sums + node_features
    g2g_k2<<<1024, 256>>>(out);         // emit edge_index + edge_attr
}